// round 2
// baseline (speedup 1.0000x reference)
#include <cuda_runtime.h>
#include <math.h>

#define BSZ 64
#define SEQ 256
#define DIN 512
#define HID 1024
#define G4  4096
#define NBLK 128

// ---------------- scratch (static device memory; no allocs allowed) --------
__device__ float g_gx[(size_t)SEQ * BSZ * G4];   // 256 MB
__device__ float g_h1[(size_t)BSZ * SEQ * HID];  // 64 MB
__device__ float g_part[4 * BSZ * G4];           // 4 MB
__device__ float g_h[BSZ * HID];

// ---------------- grid barrier state ---------------------------------------
__device__ unsigned g_barc = 0;
__device__ unsigned g_barg = 0;

__device__ __forceinline__ void grid_barrier() {
    __syncthreads();
    __threadfence();
    if (threadIdx.x == 0) {
        unsigned gen = atomicAdd(&g_barg, 0u);
        unsigned t = atomicAdd(&g_barc, 1u);
        if (t == NBLK - 1u) {
            atomicExch(&g_barc, 0u);
            atomicAdd(&g_barg, 1u);   // release new generation
        } else {
            while (atomicAdd(&g_barg, 0u) == gen) { }
        }
        __threadfence();
    }
    __syncthreads();
}

// ---------------- packed fp32x2 helpers (sm_100+) --------------------------
__device__ __forceinline__ void fma2(unsigned long long &d,
                                     unsigned long long a,
                                     unsigned long long b) {
    asm("fma.rn.f32x2 %0, %1, %2, %0;" : "+l"(d) : "l"(a), "l"(b));
}
__device__ __forceinline__ unsigned long long pack2(float v) {
    unsigned long long r;
    asm("mov.b64 %0, {%1, %1};" : "=l"(r) : "f"(v));
    return r;
}
__device__ __forceinline__ void unpack2(unsigned long long p, float &lo, float &hi) {
    asm("mov.b64 {%0, %1}, %2;" : "=f"(lo), "=f"(hi) : "l"(p));
}
__device__ __forceinline__ float sigf(float v) {
    return 1.0f / (1.0f + expf(-v));
}

// ---------------------------------------------------------------------------
// Input-projection GEMM:  gx[s][b][n] = sum_k A[m][k] * W[n][k] + bih[n]+bhh[n]
// A rows m = b*SEQ + s (row-major, stride K). M=16384, N=4096, K in {512,1024}.
// Tile: 128(M) x 64(N) x 16(K), 256 threads, thread tile 8M x 4N (4 M-pairs).
// ---------------------------------------------------------------------------
__global__ __launch_bounds__(256) void gemm_in(
    const float* __restrict__ Ain, const float* __restrict__ W,
    const float* __restrict__ bih, const float* __restrict__ bhh,
    int K, int useH1)
{
    __shared__ float As[16][130];
    __shared__ float Bs[16][68];

    const float* A = useH1 ? g_h1 : Ain;
    const int m0 = blockIdx.x * 128;
    const int n0 = blockIdx.y * 64;
    const int tid = threadIdx.x;
    const int tn = tid & 15;
    const int tm = tid >> 4;

    unsigned long long acc[4][4];
    #pragma unroll
    for (int i = 0; i < 4; i++)
        #pragma unroll
        for (int j = 0; j < 4; j++) acc[i][j] = 0ULL;

    for (int k0 = 0; k0 < K; k0 += 16) {
        #pragma unroll
        for (int i = 0; i < 2; i++) {
            int e  = tid + i * 256;
            int kq = e & 3;
            int m  = e >> 2;
            float4 v = *reinterpret_cast<const float4*>(
                A + (size_t)(m0 + m) * K + k0 + kq * 4);
            As[kq*4+0][m] = v.x; As[kq*4+1][m] = v.y;
            As[kq*4+2][m] = v.z; As[kq*4+3][m] = v.w;
        }
        {
            int kq = tid & 3;
            int n  = tid >> 2;
            float4 v = *reinterpret_cast<const float4*>(
                W + (size_t)(n0 + n) * K + k0 + kq * 4);
            Bs[kq*4+0][n] = v.x; Bs[kq*4+1][n] = v.y;
            Bs[kq*4+2][n] = v.z; Bs[kq*4+3][n] = v.w;
        }
        __syncthreads();

        #pragma unroll
        for (int k = 0; k < 16; k++) {
            unsigned long long a[4], wb[4];
            #pragma unroll
            for (int i = 0; i < 4; i++)
                a[i] = *reinterpret_cast<const unsigned long long*>(
                    &As[k][tm * 8 + i * 2]);
            float4 bv = *reinterpret_cast<const float4*>(&Bs[k][tn * 4]);
            wb[0] = pack2(bv.x); wb[1] = pack2(bv.y);
            wb[2] = pack2(bv.z); wb[3] = pack2(bv.w);
            #pragma unroll
            for (int i = 0; i < 4; i++)
                #pragma unroll
                for (int j = 0; j < 4; j++)
                    fma2(acc[i][j], a[i], wb[j]);
        }
        __syncthreads();
    }

    #pragma unroll
    for (int j = 0; j < 4; j++) {
        int n = n0 + tn * 4 + j;
        float bias = bih[n] + bhh[n];
        #pragma unroll
        for (int i = 0; i < 4; i++) {
            int m = m0 + tm * 8 + i * 2;
            float lo, hi;
            unpack2(acc[i][j], lo, hi);
            int s1 = m & (SEQ - 1), b1 = m >> 8;
            g_gx[(size_t)(s1 * BSZ + b1) * G4 + n] = lo + bias;
            int m2 = m + 1;
            int s2 = m2 & (SEQ - 1), b2 = m2 >> 8;
            g_gx[(size_t)(s2 * BSZ + b2) * G4 + n] = hi + bias;
        }
    }
}

// ---------------------------------------------------------------------------
// Persistent LSTM layer: one launch runs all SEQ timesteps.
// 128 blocks = 32 unit-groups x 4 K-slices. Per step:
//   phase A: partial GEMM  part[ks][b][g*H+u] = sum_{k slice} h[b][k]*Whh[gH+u][k]
//   barrier
//   phase B: every block updates 512 of the 65536 (b,u) elements; c in regs
//   barrier
// ---------------------------------------------------------------------------
__global__ __launch_bounds__(256) void lstm_layer(
    const float* __restrict__ Whh, int layer, float* __restrict__ out)
{
    __shared__ float hs[16][66];
    __shared__ float ws[16][130];

    const int bx  = blockIdx.x;
    const int ug  = bx & 31;
    const int ks  = bx >> 5;
    const int u0  = ug * 32;
    const int k0b = ks * 256;
    const int tid = threadIdx.x;
    const int ul  = tid & 31;
    const int ty  = tid >> 5;

    // loader coordinates (constant across chunks)
    const int hq = tid & 3;          // k-quad for h tile
    const int hb = tid >> 2;         // batch row for h tile
    const int wr0 = tid >> 2;        // w rows: wr0 and wr0+64, same k-quad hq
    const int wr1 = wr0 + 64;
    const float* wp0 = Whh + (size_t)((wr0 >> 5) * HID + u0 + (wr0 & 31)) * HID;
    const float* wp1 = Whh + (size_t)((wr1 >> 5) * HID + u0 + (wr1 & 31)) * HID;
    const float* hp  = g_h + (size_t)hb * HID;

    // update-element assignment: 2 consecutive elements of flat [b*HID+u]
    const int ebase = bx * 512 + tid * 2;
    const int eb = ebase >> 10;      // batch
    const int eu = ebase & 1023;     // unit (even)
    float cx = 0.0f, cy = 0.0f;

    // h := 0
    *reinterpret_cast<float2*>(g_h + ebase) = make_float2(0.0f, 0.0f);
    grid_barrier();

    for (int t = 0; t < SEQ; t++) {
        unsigned long long acc[4][4];
        #pragma unroll
        for (int i = 0; i < 4; i++)
            #pragma unroll
            for (int g = 0; g < 4; g++) acc[i][g] = 0ULL;

        // prefetch chunk 0
        float4 hv  = __ldcg(reinterpret_cast<const float4*>(hp  + k0b + hq * 4));
        float4 wv0 = __ldg (reinterpret_cast<const float4*>(wp0 + k0b + hq * 4));
        float4 wv1 = __ldg (reinterpret_cast<const float4*>(wp1 + k0b + hq * 4));

        for (int kc = 0; kc < 256; kc += 16) {
            __syncthreads();   // previous iteration's consumers done
            hs[hq*4+0][hb] = hv.x;  hs[hq*4+1][hb] = hv.y;
            hs[hq*4+2][hb] = hv.z;  hs[hq*4+3][hb] = hv.w;
            ws[hq*4+0][wr0] = wv0.x; ws[hq*4+1][wr0] = wv0.y;
            ws[hq*4+2][wr0] = wv0.z; ws[hq*4+3][wr0] = wv0.w;
            ws[hq*4+0][wr1] = wv1.x; ws[hq*4+1][wr1] = wv1.y;
            ws[hq*4+2][wr1] = wv1.z; ws[hq*4+3][wr1] = wv1.w;
            __syncthreads();

            if (kc + 16 < 256) {
                int k0 = k0b + kc + 16;
                hv  = __ldcg(reinterpret_cast<const float4*>(hp  + k0 + hq * 4));
                wv0 = __ldg (reinterpret_cast<const float4*>(wp0 + k0 + hq * 4));
                wv1 = __ldg (reinterpret_cast<const float4*>(wp1 + k0 + hq * 4));
            }

            #pragma unroll
            for (int k = 0; k < 16; k++) {
                unsigned long long a[4], wb[4];
                #pragma unroll
                for (int i = 0; i < 4; i++)
                    a[i] = *reinterpret_cast<const unsigned long long*>(
                        &hs[k][ty * 8 + i * 2]);
                #pragma unroll
                for (int g = 0; g < 4; g++)
                    wb[g] = pack2(ws[k][g * 32 + ul]);
                #pragma unroll
                for (int i = 0; i < 4; i++)
                    #pragma unroll
                    for (int g = 0; g < 4; g++)
                        fma2(acc[i][g], a[i], wb[g]);
            }
        }

        // write partials (L2 only — cross-SM consumers)
        const int ksb = ks * BSZ;
        #pragma unroll
        for (int g = 0; g < 4; g++) {
            int col = g * HID + u0 + ul;
            #pragma unroll
            for (int i = 0; i < 4; i++) {
                int b = ty * 8 + i * 2;
                float lo, hi;
                unpack2(acc[i][g], lo, hi);
                __stcg(&g_part[(size_t)(ksb + b)     * G4 + col], lo);
                __stcg(&g_part[(size_t)(ksb + b + 1) * G4 + col], hi);
            }
        }
        grid_barrier();

        // ---- phase B: update my 2 elements ----
        const float* gxp = g_gx + ((size_t)t * BSZ + eb) * G4 + eu;
        float2 A0 = __ldg(reinterpret_cast<const float2*>(gxp));
        float2 A1 = __ldg(reinterpret_cast<const float2*>(gxp + HID));
        float2 A2 = __ldg(reinterpret_cast<const float2*>(gxp + 2 * HID));
        float2 A3 = __ldg(reinterpret_cast<const float2*>(gxp + 3 * HID));
        #pragma unroll
        for (int s = 0; s < 4; s++) {
            const float* pp = g_part + ((size_t)s * BSZ + eb) * G4 + eu;
            float2 p0 = __ldcg(reinterpret_cast<const float2*>(pp));
            float2 p1 = __ldcg(reinterpret_cast<const float2*>(pp + HID));
            float2 p2 = __ldcg(reinterpret_cast<const float2*>(pp + 2 * HID));
            float2 p3 = __ldcg(reinterpret_cast<const float2*>(pp + 3 * HID));
            A0.x += p0.x; A0.y += p0.y;
            A1.x += p1.x; A1.y += p1.y;
            A2.x += p2.x; A2.y += p2.y;
            A3.x += p3.x; A3.y += p3.y;
        }
        float ix = sigf(A0.x),  iy = sigf(A0.y);
        float fx = sigf(A1.x),  fy = sigf(A1.y);
        float gx_ = tanhf(A2.x), gy_ = tanhf(A2.y);
        float ox = sigf(A3.x),  oy = sigf(A3.y);
        cx = fx * cx + ix * gx_;
        cy = fy * cy + iy * gy_;
        float hx = ox * tanhf(cx);
        float hy = oy * tanhf(cy);
        __stcg(reinterpret_cast<float2*>(g_h + ebase), make_float2(hx, hy));

        if (layer == 0) {
            *reinterpret_cast<float2*>(
                g_h1 + ((size_t)eb * SEQ + t) * HID + eu) = make_float2(hx, hy);
        } else {
            float rx = hx > 0.0f ? hx : 0.0f;
            float ry = hy > 0.0f ? hy : 0.0f;
            *reinterpret_cast<float2*>(
                out + ((size_t)eb * SEQ + t) * HID + eu) =
                make_float2(sigf(-(-rx)), sigf(-(-ry)));
        }
        grid_barrier();
    }
}

// ---------------------------------------------------------------------------
extern "C" void kernel_launch(void* const* d_in, const int* in_sizes, int n_in,
                              void* d_out, int out_size)
{
    const float* x    = (const float*)d_in[0];
    const float* Wih0 = (const float*)d_in[1];
    const float* Whh0 = (const float*)d_in[2];
    const float* bih0 = (const float*)d_in[3];
    const float* bhh0 = (const float*)d_in[4];
    const float* Wih1 = (const float*)d_in[5];
    const float* Whh1 = (const float*)d_in[6];
    const float* bih1 = (const float*)d_in[7];
    const float* bhh1 = (const float*)d_in[8];
    float* out = (float*)d_out;

    dim3 gg(128, 64);  // M/128 x N/64

    gemm_in<<<gg, 256>>>(x, Wih0, bih0, bhh0, DIN, 0);
    lstm_layer<<<NBLK, 256>>>(Whh0, 0, out);

    gemm_in<<<gg, 256>>>(nullptr, Wih1, bih1, bhh1, HID, 1);
    lstm_layer<<<NBLK, 256>>>(Whh1, 1, out);
}

// round 6
// speedup vs baseline: 1.3679x; 1.3679x over previous
#include <cuda_runtime.h>
#include <cuda_bf16.h>
#include <math.h>
#include <stdint.h>

#define BSZ 64
#define SEQ 256
#define DIN 512
#define HID 1024
#define G4  4096
#define RCTA 128

// ---------------- scratch (static device memory; no allocs allowed) --------
__device__ __align__(16) float g_gx[(size_t)SEQ * BSZ * G4];   // 256 MB
__device__ __align__(16) float g_h1[(size_t)BSZ * SEQ * HID];  // 64 MB
__device__ __align__(16) __nv_bfloat16 g_wp_hi[(size_t)G4 * HID];  // 8 MB
__device__ __align__(16) __nv_bfloat16 g_wp_lo[(size_t)G4 * HID];  // 8 MB
__device__ __align__(16) __nv_bfloat16 g_hbf_hi[2][BSZ * HID];
__device__ __align__(16) __nv_bfloat16 g_hbf_lo[2][BSZ * HID];

// ---------------- grid barrier ---------------------------------------------
__device__ unsigned g_barc = 0;
__device__ unsigned g_barg = 0;

__device__ __forceinline__ void grid_barrier(unsigned nblk) {
    __syncthreads();
    __threadfence();
    if (threadIdx.x == 0) {
        unsigned gen = atomicAdd(&g_barg, 0u);
        unsigned t = atomicAdd(&g_barc, 1u);
        if (t == nblk - 1u) {
            atomicExch(&g_barc, 0u);
            atomicAdd(&g_barg, 1u);
        } else {
            while (atomicAdd(&g_barg, 0u) == gen) { }
        }
        __threadfence();
    }
    __syncthreads();
}

// ---------------- scalar helpers -------------------------------------------
__device__ __forceinline__ void fma2(unsigned long long &d,
                                     unsigned long long a,
                                     unsigned long long b) {
    asm("fma.rn.f32x2 %0, %1, %2, %0;" : "+l"(d) : "l"(a), "l"(b));
}
__device__ __forceinline__ unsigned long long pack2(float v) {
    unsigned long long r;
    asm("mov.b64 %0, {%1, %1};" : "=l"(r) : "f"(v));
    return r;
}
__device__ __forceinline__ void unpack2(unsigned long long p, float &lo, float &hi) {
    asm("mov.b64 {%0, %1}, %2;" : "=f"(lo), "=f"(hi) : "l"(p));
}
__device__ __forceinline__ float sigf(float v) {
    return 1.0f / (1.0f + expf(-v));
}
__device__ __forceinline__ uint32_t pack_bf2(float a, float b) {
    __nv_bfloat162 t = __floats2bfloat162_rn(a, b);
    return *reinterpret_cast<uint32_t*>(&t);
}
__device__ __forceinline__ uint32_t smem_u32(const void* p) {
    uint32_t a;
    asm("{ .reg .u64 t; cvta.to.shared.u64 t, %1; cvt.u32.u64 %0, t; }"
        : "=r"(a) : "l"(p));
    return a;
}

// ---------------- HMMA helpers ---------------------------------------------
__device__ __forceinline__ void ldsm4(uint32_t &r0, uint32_t &r1,
                                      uint32_t &r2, uint32_t &r3,
                                      uint32_t addr) {
    asm volatile("ldmatrix.sync.aligned.m8n8.x4.shared.b16 {%0,%1,%2,%3}, [%4];"
                 : "=r"(r0), "=r"(r1), "=r"(r2), "=r"(r3) : "r"(addr));
}
__device__ __forceinline__ void mma16816(float* d, const uint32_t* a,
                                         uint32_t b0, uint32_t b1) {
    asm volatile(
        "mma.sync.aligned.m16n8k16.row.col.f32.bf16.bf16.f32 "
        "{%0,%1,%2,%3}, {%4,%5,%6,%7}, {%8,%9}, {%0,%1,%2,%3};"
        : "+f"(d[0]), "+f"(d[1]), "+f"(d[2]), "+f"(d[3])
        : "r"(a[0]), "r"(a[1]), "r"(a[2]), "r"(a[3]), "r"(b0), "r"(b1));
}

// ---------------------------------------------------------------------------
// Input-projection GEMM (fp32 f32x2 — known correct).
// ---------------------------------------------------------------------------
__global__ __launch_bounds__(256) void gemm_in(
    const float* __restrict__ Ain, const float* __restrict__ W,
    const float* __restrict__ bih, const float* __restrict__ bhh,
    int K, int useH1)
{
    __shared__ float As[16][130];
    __shared__ float Bs[16][68];

    const float* A = useH1 ? g_h1 : Ain;
    const int m0 = blockIdx.x * 128;
    const int n0 = blockIdx.y * 64;
    const int tid = threadIdx.x;
    const int tn = tid & 15;
    const int tm = tid >> 4;

    unsigned long long acc[4][4];
    #pragma unroll
    for (int i = 0; i < 4; i++)
        #pragma unroll
        for (int j = 0; j < 4; j++) acc[i][j] = 0ULL;

    for (int k0 = 0; k0 < K; k0 += 16) {
        #pragma unroll
        for (int i = 0; i < 2; i++) {
            int e  = tid + i * 256;
            int kq = e & 3;
            int m  = e >> 2;
            float4 v = *reinterpret_cast<const float4*>(
                A + (size_t)(m0 + m) * K + k0 + kq * 4);
            As[kq*4+0][m] = v.x; As[kq*4+1][m] = v.y;
            As[kq*4+2][m] = v.z; As[kq*4+3][m] = v.w;
        }
        {
            int kq = tid & 3;
            int n  = tid >> 2;
            float4 v = *reinterpret_cast<const float4*>(
                W + (size_t)(n0 + n) * K + k0 + kq * 4);
            Bs[kq*4+0][n] = v.x; Bs[kq*4+1][n] = v.y;
            Bs[kq*4+2][n] = v.z; Bs[kq*4+3][n] = v.w;
        }
        __syncthreads();

        #pragma unroll
        for (int k = 0; k < 16; k++) {
            unsigned long long a[4], wb[4];
            #pragma unroll
            for (int i = 0; i < 4; i++)
                a[i] = *reinterpret_cast<const unsigned long long*>(
                    &As[k][tm * 8 + i * 2]);
            float4 bv = *reinterpret_cast<const float4*>(&Bs[k][tn * 4]);
            wb[0] = pack2(bv.x); wb[1] = pack2(bv.y);
            wb[2] = pack2(bv.z); wb[3] = pack2(bv.w);
            #pragma unroll
            for (int i = 0; i < 4; i++)
                #pragma unroll
                for (int j = 0; j < 4; j++)
                    fma2(acc[i][j], a[i], wb[j]);
        }
        __syncthreads();
    }

    #pragma unroll
    for (int j = 0; j < 4; j++) {
        int n = n0 + tn * 4 + j;
        float bias = bih[n] + bhh[n];
        #pragma unroll
        for (int i = 0; i < 4; i++) {
            int m = m0 + tm * 8 + i * 2;
            float lo, hi;
            unpack2(acc[i][j], lo, hi);
            int s1 = m & (SEQ - 1), b1 = m >> 8;
            g_gx[(size_t)(s1 * BSZ + b1) * G4 + n] = lo + bias;
            int m2 = m + 1;
            int s2 = m2 & (SEQ - 1), b2 = m2 >> 8;
            g_gx[(size_t)(s2 * BSZ + b2) * G4 + n] = hi + bias;
        }
    }
}

// ---------------------------------------------------------------------------
// Permute + split Whh -> bf16 hi/lo.
// Permuted row r = j*32 + g*8 + uu  <-  original row g*1024 + j*8 + uu.
// ---------------------------------------------------------------------------
__global__ __launch_bounds__(256) void convert_w(const float* __restrict__ Whh)
{
    int r  = blockIdx.x;
    int j  = r >> 5;
    int g  = (r >> 3) & 3;
    int uu = r & 7;
    const float* src = Whh + (size_t)(g * HID + j * 8 + uu) * HID;
    __nv_bfloat16* hi = g_wp_hi + (size_t)r * HID;
    __nv_bfloat16* lo = g_wp_lo + (size_t)r * HID;
    for (int k = threadIdx.x; k < HID; k += 256) {
        float w = src[k];
        __nv_bfloat16 h = __float2bfloat16(w);
        hi[k] = h;
        lo[k] = __float2bfloat16(w - __bfloat162float(h));
    }
}

// ---------------------------------------------------------------------------
// Persistent HMMA LSTM layer. 128 CTAs x 256 threads. STATIC 48KB smem,
// SINGLE stage, register double-buffering (no cudaFuncSetAttribute).
// CTA j: D[32 x 64] = Wp[j*32 .. j*32+31] . h^T  via bf16x3 mma.sync.
// One grid barrier per step; h ping-pong buffers (read t&1, write (t+1)&1).
// ---------------------------------------------------------------------------
// smem stage layout (bytes): AHI[32][128]bf16 @0 (8K), ALO @8K,
// BHI[64][128] @16K (16K), BLO @32K. Total 48K. D exchange aliases @0.
#define OFF_ALO  8192
#define OFF_BHI  16384
#define OFF_BLO  32768
#define DPITCH   68

// 16B-unit XOR swizzle on 256-byte rows
__device__ __forceinline__ uint32_t swz(int row, int unit) {
    return (uint32_t)(row * 256 + ((unit ^ (row & 15)) << 4));
}

__global__ __launch_bounds__(256) void lstm_mma(int layer, float* __restrict__ out)
{
    __shared__ __align__(16) char smem[49152];
    const uint32_t sbase = smem_u32(smem);
    const int tid  = threadIdx.x;
    const int wid  = tid >> 5;
    const int lane = tid & 31;
    const int j    = blockIdx.x;

    // ---- loader coords ----
    const int ar0 = tid >> 4,  ac0 = tid & 15;
    const __nv_bfloat16* wjh = g_wp_hi + (size_t)(j * 32) * HID;
    const __nv_bfloat16* wjl = g_wp_lo + (size_t)(j * 32) * HID;

    // ---- mma coords ----
    const int mh = wid & 1;          // m-half (16 rows)
    const int nt = wid >> 1;         // n-tile (16 batches)
    const int arow = mh * 16 + (lane & 15);
    const int brow = nt * 16 + (lane & 15);
    const int uoff = lane >> 4;      // 0/1: k-half unit offset
    const int arsw = arow & 15;
    const int brsw = brow & 15;

    // ---- epilogue coords: batch b, units u2,u2+1 ----
    const int b  = tid & 63;
    const int up = tid >> 6;
    const int u2 = up * 2;
    float cs0 = 0.0f, cs1 = 0.0f;

    // zero h buffer 0
    {
        unsigned* zh = reinterpret_cast<unsigned*>(g_hbf_hi[0]);
        unsigned* zl = reinterpret_cast<unsigned*>(g_hbf_lo[0]);
        for (int i = j * 256 + tid; i < BSZ * HID / 2; i += RCTA * 256)
        { __stcg(zh + i, 0u); __stcg(zl + i, 0u); }
    }
    grid_barrier(RCTA);

    uint4 pa_h[2], pa_l[2], pb_h[4], pb_l[4];

    for (int t = 0; t < SEQ; t++) {
        const __nv_bfloat16* hbh = g_hbf_hi[t & 1];
        const __nv_bfloat16* hbl = g_hbf_lo[t & 1];

        // prefetch gx for epilogue (overlaps everything below)
        const float* gxp = g_gx + ((size_t)t * BSZ + b) * G4 + j * 8;
        float gx0 = __ldg(gxp + u2),            gx1 = __ldg(gxp + u2 + 1);
        float gf0 = __ldg(gxp + HID + u2),      gf1 = __ldg(gxp + HID + u2 + 1);
        float gg0 = __ldg(gxp + 2*HID + u2),    gg1 = __ldg(gxp + 2*HID + u2 + 1);
        float go0 = __ldg(gxp + 3*HID + u2),    go1 = __ldg(gxp + 3*HID + u2 + 1);

        float acc[8];
        #pragma unroll
        for (int i = 0; i < 8; i++) acc[i] = 0.0f;

        // prefetch chunk 0 into registers
        #pragma unroll
        for (int i = 0; i < 2; i++) {
            size_t go = (size_t)(ar0 + i * 16) * HID + ac0 * 8;
            pa_h[i] = *reinterpret_cast<const uint4*>(wjh + go);
            pa_l[i] = *reinterpret_cast<const uint4*>(wjl + go);
        }
        #pragma unroll
        for (int i = 0; i < 4; i++) {
            size_t go = (size_t)(ar0 + i * 16) * HID + ac0 * 8;
            pb_h[i] = __ldcg(reinterpret_cast<const uint4*>(hbh + go));
            pb_l[i] = __ldcg(reinterpret_cast<const uint4*>(hbl + go));
        }

        for (int kc = 0; kc < 8; kc++) {
            // WAR: previous chunk's ldmatrix reads (and prior-step D reads)
            // must finish before overwriting the single stage.
            __syncthreads();
            #pragma unroll
            for (int i = 0; i < 2; i++) {
                uint32_t so = swz(ar0 + i * 16, ac0);
                *reinterpret_cast<uint4*>(smem + so) = pa_h[i];
                *reinterpret_cast<uint4*>(smem + OFF_ALO + so) = pa_l[i];
            }
            #pragma unroll
            for (int i = 0; i < 4; i++) {
                uint32_t so = swz(ar0 + i * 16, ac0);
                *reinterpret_cast<uint4*>(smem + OFF_BHI + so) = pb_h[i];
                *reinterpret_cast<uint4*>(smem + OFF_BLO + so) = pb_l[i];
            }
            __syncthreads();

            // prefetch next chunk into registers (overlaps the MMAs below)
            if (kc < 7) {
                int cb = (kc + 1) * 128 + ac0 * 8;
                #pragma unroll
                for (int i = 0; i < 2; i++) {
                    size_t go = (size_t)(ar0 + i * 16) * HID + cb;
                    pa_h[i] = *reinterpret_cast<const uint4*>(wjh + go);
                    pa_l[i] = *reinterpret_cast<const uint4*>(wjl + go);
                }
                #pragma unroll
                for (int i = 0; i < 4; i++) {
                    size_t go = (size_t)(ar0 + i * 16) * HID + cb;
                    pb_h[i] = __ldcg(reinterpret_cast<const uint4*>(hbh + go));
                    pb_l[i] = __ldcg(reinterpret_cast<const uint4*>(hbl + go));
                }
            }

            // mma over 8 k-steps of this chunk
            const uint32_t sA = sbase;
            const uint32_t sB = sbase + OFF_BHI;
            #pragma unroll
            for (int ks = 0; ks < 8; ks++) {
                int un = ks * 2 + uoff;
                uint32_t aaddr = sA + (uint32_t)(arow * 256 + ((un ^ arsw) << 4));
                uint32_t baddr = sB + (uint32_t)(brow * 256 + ((un ^ brsw) << 4));
                uint32_t ah[4], al[4], bh[4], bl[4];
                ldsm4(ah[0], ah[1], ah[2], ah[3], aaddr);
                ldsm4(al[0], al[1], al[2], al[3], aaddr + OFF_ALO);
                ldsm4(bh[0], bh[1], bh[2], bh[3], baddr);
                ldsm4(bl[0], bl[1], bl[2], bl[3], baddr + (OFF_BLO - OFF_BHI));
                mma16816(acc,     ah, bh[0], bh[2]);
                mma16816(acc,     ah, bl[0], bl[2]);
                mma16816(acc,     al, bh[0], bh[2]);
                mma16816(acc + 4, ah, bh[1], bh[3]);
                mma16816(acc + 4, ah, bl[1], bl[3]);
                mma16816(acc + 4, al, bh[1], bh[3]);
            }
        }
        __syncthreads();   // stage reads done; safe to alias D over it

        // ---- D exchange via smem ----
        float* D = reinterpret_cast<float*>(smem);
        {
            int col = nt * 16 + (lane & 3) * 2;
            int row0 = mh * 16 + (lane >> 2);
            *reinterpret_cast<float2*>(&D[row0 * DPITCH + col]) =
                make_float2(acc[0], acc[1]);
            *reinterpret_cast<float2*>(&D[(row0 + 8) * DPITCH + col]) =
                make_float2(acc[2], acc[3]);
            *reinterpret_cast<float2*>(&D[row0 * DPITCH + col + 8]) =
                make_float2(acc[4], acc[5]);
            *reinterpret_cast<float2*>(&D[(row0 + 8) * DPITCH + col + 8]) =
                make_float2(acc[6], acc[7]);
        }
        __syncthreads();

        // ---- gate update for (b, u2) and (b, u2+1) ----
        float pi0 = D[(0*8 + u2) * DPITCH + b] + gx0;
        float pf0 = D[(1*8 + u2) * DPITCH + b] + gf0;
        float pg0 = D[(2*8 + u2) * DPITCH + b] + gg0;
        float po0 = D[(3*8 + u2) * DPITCH + b] + go0;
        float pi1 = D[(0*8 + u2 + 1) * DPITCH + b] + gx1;
        float pf1 = D[(1*8 + u2 + 1) * DPITCH + b] + gf1;
        float pg1 = D[(2*8 + u2 + 1) * DPITCH + b] + gg1;
        float po1 = D[(3*8 + u2 + 1) * DPITCH + b] + go1;

        cs0 = sigf(pf0) * cs0 + sigf(pi0) * tanhf(pg0);
        cs1 = sigf(pf1) * cs1 + sigf(pi1) * tanhf(pg1);
        float h0 = sigf(po0) * tanhf(cs0);
        float h1 = sigf(po1) * tanhf(cs1);

        // write h (bf16 hi/lo) into the other buffer
        {
            __nv_bfloat16 h0h = __float2bfloat16(h0);
            __nv_bfloat16 h1h = __float2bfloat16(h1);
            float h0hf = __bfloat162float(h0h);
            float h1hf = __bfloat162float(h1h);
            int wbuf = (t + 1) & 1;
            int idx2 = (b * HID + j * 8 + u2) >> 1;
            __stcg(reinterpret_cast<uint32_t*>(g_hbf_hi[wbuf]) + idx2,
                   pack_bf2(h0hf, h1hf));
            __stcg(reinterpret_cast<uint32_t*>(g_hbf_lo[wbuf]) + idx2,
                   pack_bf2(h0 - h0hf, h1 - h1hf));
        }

        // layer output
        if (layer == 0) {
            *reinterpret_cast<float2*>(
                g_h1 + ((size_t)b * SEQ + t) * HID + j * 8 + u2) =
                make_float2(h0, h1);
        } else {
            float r0 = h0 > 0.0f ? h0 : 0.0f;
            float r1 = h1 > 0.0f ? h1 : 0.0f;
            *reinterpret_cast<float2*>(
                out + ((size_t)b * SEQ + t) * HID + j * 8 + u2) =
                make_float2(sigf(r0), sigf(r1));
        }

        grid_barrier(RCTA);
    }
}

// ---------------------------------------------------------------------------
extern "C" void kernel_launch(void* const* d_in, const int* in_sizes, int n_in,
                              void* d_out, int out_size)
{
    const float* x    = (const float*)d_in[0];
    const float* Wih0 = (const float*)d_in[1];
    const float* Whh0 = (const float*)d_in[2];
    const float* bih0 = (const float*)d_in[3];
    const float* bhh0 = (const float*)d_in[4];
    const float* Wih1 = (const float*)d_in[5];
    const float* Whh1 = (const float*)d_in[6];
    const float* bih1 = (const float*)d_in[7];
    const float* bhh1 = (const float*)d_in[8];
    float* out = (float*)d_out;

    dim3 gg(128, 64);  // M/128 x N/64

    convert_w<<<G4, 256>>>(Whh0);
    gemm_in<<<gg, 256>>>(x, Wih0, bih0, bhh0, DIN, 0);
    lstm_mma<<<RCTA, 256>>>(0, out);

    convert_w<<<G4, 256>>>(Whh1);
    gemm_in<<<gg, 256>>>(nullptr, Wih1, bih1, bhh1, HID, 1);
    lstm_mma<<<RCTA, 256>>>(1, out);
}

// round 8
// speedup vs baseline: 1.6543x; 1.2094x over previous
#include <cuda_runtime.h>
#include <cuda_bf16.h>
#include <math.h>
#include <stdint.h>

#define BSZ 64
#define SEQ 256
#define DIN 512
#define HID 1024
#define G4  4096
#define MTOT 16384
#define RCTA 128

// ---------------- scratch (static device memory; no allocs allowed) --------
__device__ __align__(16) float g_gx[(size_t)SEQ * BSZ * G4];   // 256 MB, [s][b][n]
__device__ __align__(16) float g_h1[(size_t)BSZ * SEQ * HID];  // 64 MB
__device__ __align__(16) __nv_bfloat16 g_wp_hi[(size_t)G4 * HID];   // recurrence W (permuted)
__device__ __align__(16) __nv_bfloat16 g_wp_lo[(size_t)G4 * HID];
__device__ __align__(16) __nv_bfloat16 g_wih_hi[(size_t)G4 * HID];  // input W
__device__ __align__(16) __nv_bfloat16 g_wih_lo[(size_t)G4 * HID];
__device__ __align__(16) __nv_bfloat16 g_xbf_hi[(size_t)MTOT * HID];// x / h1 split
__device__ __align__(16) __nv_bfloat16 g_xbf_lo[(size_t)MTOT * HID];
__device__ __align__(16) __nv_bfloat16 g_hbf_hi[2][BSZ * HID];
__device__ __align__(16) __nv_bfloat16 g_hbf_lo[2][BSZ * HID];

// ---------------- grid barrier ---------------------------------------------
__device__ unsigned g_barc = 0;
__device__ unsigned g_barg = 0;

__device__ __forceinline__ void grid_barrier(unsigned nblk) {
    __syncthreads();
    __threadfence();
    if (threadIdx.x == 0) {
        unsigned gen = atomicAdd(&g_barg, 0u);
        unsigned t = atomicAdd(&g_barc, 1u);
        if (t == nblk - 1u) {
            atomicExch(&g_barc, 0u);
            atomicAdd(&g_barg, 1u);
        } else {
            while (atomicAdd(&g_barg, 0u) == gen) { }
        }
        __threadfence();
    }
    __syncthreads();
}

// ---------------- scalar helpers -------------------------------------------
__device__ __forceinline__ float sigf(float v) {
    return 1.0f / (1.0f + expf(-v));
}
__device__ __forceinline__ uint32_t pack_bf2(float a, float b) {
    __nv_bfloat162 t = __floats2bfloat162_rn(a, b);
    return *reinterpret_cast<uint32_t*>(&t);
}
__device__ __forceinline__ uint32_t smem_u32(const void* p) {
    uint32_t a;
    asm("{ .reg .u64 t; cvta.to.shared.u64 t, %1; cvt.u32.u64 %0, t; }"
        : "=r"(a) : "l"(p));
    return a;
}

// ---------------- HMMA helpers ---------------------------------------------
__device__ __forceinline__ void ldsm4(uint32_t &r0, uint32_t &r1,
                                      uint32_t &r2, uint32_t &r3,
                                      uint32_t addr) {
    asm volatile("ldmatrix.sync.aligned.m8n8.x4.shared.b16 {%0,%1,%2,%3}, [%4];"
                 : "=r"(r0), "=r"(r1), "=r"(r2), "=r"(r3) : "r"(addr));
}
__device__ __forceinline__ void mma16816(float* d, const uint32_t* a,
                                         uint32_t b0, uint32_t b1) {
    asm volatile(
        "mma.sync.aligned.m16n8k16.row.col.f32.bf16.bf16.f32 "
        "{%0,%1,%2,%3}, {%4,%5,%6,%7}, {%8,%9}, {%0,%1,%2,%3};"
        : "+f"(d[0]), "+f"(d[1]), "+f"(d[2]), "+f"(d[3])
        : "r"(a[0]), "r"(a[1]), "r"(a[2]), "r"(a[3]), "r"(b0), "r"(b1));
}

// ---------------------------------------------------------------------------
// fp32 -> bf16 hi/lo splits
// ---------------------------------------------------------------------------
__global__ __launch_bounds__(256) void convert_x(const float* __restrict__ x,
                                                 int n)
{
    for (int i = blockIdx.x * 256 + threadIdx.x; i < n; i += gridDim.x * 256) {
        float w = x[i];
        __nv_bfloat16 h = __float2bfloat16(w);
        g_xbf_hi[i] = h;
        g_xbf_lo[i] = __float2bfloat16(w - __bfloat162float(h));
    }
}

__global__ __launch_bounds__(256) void convert_h1()
{
    const int n = MTOT * HID;
    for (int i = blockIdx.x * 256 + threadIdx.x; i < n; i += gridDim.x * 256) {
        float w = g_h1[i];
        __nv_bfloat16 h = __float2bfloat16(w);
        g_xbf_hi[i] = h;
        g_xbf_lo[i] = __float2bfloat16(w - __bfloat162float(h));
    }
}

__global__ __launch_bounds__(256) void convert_wih(const float* __restrict__ W,
                                                   int n)
{
    for (int i = blockIdx.x * 256 + threadIdx.x; i < n; i += gridDim.x * 256) {
        float w = W[i];
        __nv_bfloat16 h = __float2bfloat16(w);
        g_wih_hi[i] = h;
        g_wih_lo[i] = __float2bfloat16(w - __bfloat162float(h));
    }
}

// Permute + split Whh for the recurrence (R6 proven).
// Permuted row r = j*32 + g*8 + uu  <-  original row g*1024 + j*8 + uu.
__global__ __launch_bounds__(256) void convert_w(const float* __restrict__ Whh)
{
    int r  = blockIdx.x;
    int j  = r >> 5;
    int g  = (r >> 3) & 3;
    int uu = r & 7;
    const float* src = Whh + (size_t)(g * HID + j * 8 + uu) * HID;
    __nv_bfloat16* hi = g_wp_hi + (size_t)r * HID;
    __nv_bfloat16* lo = g_wp_lo + (size_t)r * HID;
    for (int k = threadIdx.x; k < HID; k += 256) {
        float w = src[k];
        __nv_bfloat16 h = __float2bfloat16(w);
        hi[k] = h;
        lo[k] = __float2bfloat16(w - __bfloat162float(h));
    }
}

// ---------------------------------------------------------------------------
// HMMA input-projection GEMM (bf16x3):
//   gx[s][b][n] = sum_k X[m][k]*W[n][k] + bih[n]+bhh[n],   m = b*SEQ+s
// CTA: 128 m-rows (A=X) x 64 n-rows (B=W), K chunks of 64. Static 48KB,
// single stage + register prefetch (exact R6 lstm_mma pipeline pattern).
// smem: A_hi @0 (16K), A_lo @16K, B_hi @32K (8K), B_lo @40K.
// 8 warps = 4(m-quarters) x 2(n-halves); warp tile 32x32.
// ---------------------------------------------------------------------------
__global__ __launch_bounds__(256) void gemm_hmma(
    const float* __restrict__ bih, const float* __restrict__ bhh, int K)
{
    __shared__ __align__(16) char smem[49152];
    const uint32_t sbase = smem_u32(smem);
    const int tid = threadIdx.x;
    const int wid = tid >> 5;
    const int lane = tid & 31;
    const int n0 = blockIdx.x * 64;
    const int m0 = blockIdx.y * 128;

    // loader coords: rows lr(+i*32), 16B unit lu
    const int lr = tid >> 3;
    const int lu = tid & 7;
    const uint32_t so = (uint32_t)(lr * 128 + ((lu ^ (lr & 7)) << 4));

    // mma coords
    const int wm = wid >> 1;                   // 0..3: 32 m-rows
    const int wn = wid & 1;                    // 0..1: 32 n-cols
    const int arow = wm * 32 + (lane & 15);    // +16 for fa=1
    const int brow = wn * 32 + (lane & 15);    // +16 for fbg=1
    const int asw  = lane & 7;                 // row&7 invariant under +16/+32
    const int uoff = lane >> 4;

    float acc[2][4][4];
    #pragma unroll
    for (int a = 0; a < 2; a++)
        #pragma unroll
        for (int f = 0; f < 4; f++)
            #pragma unroll
            for (int q = 0; q < 4; q++) acc[a][f][q] = 0.0f;

    const int nch = K >> 6;
    uint4 ra_h[4], ra_l[4], rb_h[2], rb_l[2];

    // prefetch chunk 0
    {
        int cb = lu * 8;
        #pragma unroll
        for (int i = 0; i < 4; i++) {
            size_t o = (size_t)(m0 + lr + i * 32) * K + cb;
            ra_h[i] = *reinterpret_cast<const uint4*>(g_xbf_hi + o);
            ra_l[i] = *reinterpret_cast<const uint4*>(g_xbf_lo + o);
        }
        #pragma unroll
        for (int i = 0; i < 2; i++) {
            size_t o = (size_t)(n0 + lr + i * 32) * K + cb;
            rb_h[i] = *reinterpret_cast<const uint4*>(g_wih_hi + o);
            rb_l[i] = *reinterpret_cast<const uint4*>(g_wih_lo + o);
        }
    }

    for (int kc = 0; kc < nch; kc++) {
        __syncthreads();   // WAR on the single stage
        #pragma unroll
        for (int i = 0; i < 4; i++) {
            uint32_t s2 = so + (uint32_t)(i * 32 * 128);
            *reinterpret_cast<uint4*>(smem + s2)         = ra_h[i];
            *reinterpret_cast<uint4*>(smem + 16384 + s2) = ra_l[i];
        }
        #pragma unroll
        for (int i = 0; i < 2; i++) {
            uint32_t s2 = so + (uint32_t)(i * 32 * 128);
            *reinterpret_cast<uint4*>(smem + 32768 + s2) = rb_h[i];
            *reinterpret_cast<uint4*>(smem + 40960 + s2) = rb_l[i];
        }
        __syncthreads();

        if (kc + 1 < nch) {
            int cb = (kc + 1) * 64 + lu * 8;
            #pragma unroll
            for (int i = 0; i < 4; i++) {
                size_t o = (size_t)(m0 + lr + i * 32) * K + cb;
                ra_h[i] = *reinterpret_cast<const uint4*>(g_xbf_hi + o);
                ra_l[i] = *reinterpret_cast<const uint4*>(g_xbf_lo + o);
            }
            #pragma unroll
            for (int i = 0; i < 2; i++) {
                size_t o = (size_t)(n0 + lr + i * 32) * K + cb;
                rb_h[i] = *reinterpret_cast<const uint4*>(g_wih_hi + o);
                rb_l[i] = *reinterpret_cast<const uint4*>(g_wih_lo + o);
            }
        }

        #pragma unroll
        for (int ks = 0; ks < 4; ks++) {
            int un = ks * 2 + uoff;
            uint32_t ah[2][4], al[2][4], bh[2][4], bl[2][4];
            #pragma unroll
            for (int fa = 0; fa < 2; fa++) {
                uint32_t aaddr = sbase +
                    (uint32_t)((arow + fa * 16) * 128 + ((un ^ asw) << 4));
                ldsm4(ah[fa][0], ah[fa][1], ah[fa][2], ah[fa][3], aaddr);
                ldsm4(al[fa][0], al[fa][1], al[fa][2], al[fa][3], aaddr + 16384);
            }
            #pragma unroll
            for (int fbg = 0; fbg < 2; fbg++) {
                uint32_t baddr = sbase + 32768 +
                    (uint32_t)((brow + fbg * 16) * 128 + ((un ^ asw) << 4));
                ldsm4(bh[fbg][0], bh[fbg][1], bh[fbg][2], bh[fbg][3], baddr);
                ldsm4(bl[fbg][0], bl[fbg][1], bl[fbg][2], bl[fbg][3], baddr + 8192);
            }
            // bf16x3: hi*hi + hi*lo + lo*hi
            #pragma unroll
            for (int fa = 0; fa < 2; fa++)
                #pragma unroll
                for (int fbg = 0; fbg < 2; fbg++) {
                    mma16816(acc[fa][fbg*2+0], ah[fa], bh[fbg][0], bh[fbg][2]);
                    mma16816(acc[fa][fbg*2+0], ah[fa], bl[fbg][0], bl[fbg][2]);
                    mma16816(acc[fa][fbg*2+0], al[fa], bh[fbg][0], bh[fbg][2]);
                    mma16816(acc[fa][fbg*2+1], ah[fa], bh[fbg][1], bh[fbg][3]);
                    mma16816(acc[fa][fbg*2+1], ah[fa], bl[fbg][1], bl[fbg][3]);
                    mma16816(acc[fa][fbg*2+1], al[fa], bh[fbg][1], bh[fbg][3]);
                }
        }
    }

    // epilogue: bias + store C frags to gx[s][b][n] (float2 along n)
    #pragma unroll
    for (int fa = 0; fa < 2; fa++) {
        int r0 = m0 + wm * 32 + fa * 16 + (lane >> 2);   // global m, row of d0,d1
        int r8 = r0 + 8;                                  // row of d2,d3
        int s0 = r0 & (SEQ - 1), b0 = r0 >> 8;
        int s8 = r8 & (SEQ - 1), b8 = r8 >> 8;
        float* p0 = g_gx + (size_t)(s0 * BSZ + b0) * G4;
        float* p8 = g_gx + (size_t)(s8 * BSZ + b8) * G4;
        #pragma unroll
        for (int fb = 0; fb < 4; fb++) {
            int c = n0 + wn * 32 + (fb >> 1) * 16 + (fb & 1) * 8 + (lane & 3) * 2;
            float bc0 = __ldg(bih + c) + __ldg(bhh + c);
            float bc1 = __ldg(bih + c + 1) + __ldg(bhh + c + 1);
            *reinterpret_cast<float2*>(p0 + c) =
                make_float2(acc[fa][fb][0] + bc0, acc[fa][fb][1] + bc1);
            *reinterpret_cast<float2*>(p8 + c) =
                make_float2(acc[fa][fb][2] + bc0, acc[fa][fb][3] + bc1);
        }
    }
}

// ---------------------------------------------------------------------------
// Persistent HMMA LSTM layer — EXACT R6 source (proven pass).
// ---------------------------------------------------------------------------
#define OFF_ALO  8192
#define OFF_BHI  16384
#define OFF_BLO  32768
#define DPITCH   68

__device__ __forceinline__ uint32_t swz(int row, int unit) {
    return (uint32_t)(row * 256 + ((unit ^ (row & 15)) << 4));
}

__global__ __launch_bounds__(256) void lstm_mma(int layer, float* __restrict__ out)
{
    __shared__ __align__(16) char smem[49152];
    const uint32_t sbase = smem_u32(smem);
    const int tid  = threadIdx.x;
    const int wid  = tid >> 5;
    const int lane = tid & 31;
    const int j    = blockIdx.x;

    const int ar0 = tid >> 4,  ac0 = tid & 15;
    const __nv_bfloat16* wjh = g_wp_hi + (size_t)(j * 32) * HID;
    const __nv_bfloat16* wjl = g_wp_lo + (size_t)(j * 32) * HID;

    const int mh = wid & 1;
    const int nt = wid >> 1;
    const int arow = mh * 16 + (lane & 15);
    const int brow = nt * 16 + (lane & 15);
    const int uoff = lane >> 4;
    const int arsw = arow & 15;
    const int brsw = brow & 15;

    const int b  = tid & 63;
    const int up = tid >> 6;
    const int u2 = up * 2;
    float cs0 = 0.0f, cs1 = 0.0f;

    {
        unsigned* zh = reinterpret_cast<unsigned*>(g_hbf_hi[0]);
        unsigned* zl = reinterpret_cast<unsigned*>(g_hbf_lo[0]);
        for (int i = j * 256 + tid; i < BSZ * HID / 2; i += RCTA * 256)
        { __stcg(zh + i, 0u); __stcg(zl + i, 0u); }
    }
    grid_barrier(RCTA);

    uint4 pa_h[2], pa_l[2], pb_h[4], pb_l[4];

    for (int t = 0; t < SEQ; t++) {
        const __nv_bfloat16* hbh = g_hbf_hi[t & 1];
        const __nv_bfloat16* hbl = g_hbf_lo[t & 1];

        const float* gxp = g_gx + ((size_t)t * BSZ + b) * G4 + j * 8;
        float gx0 = __ldg(gxp + u2),            gx1 = __ldg(gxp + u2 + 1);
        float gf0 = __ldg(gxp + HID + u2),      gf1 = __ldg(gxp + HID + u2 + 1);
        float gg0 = __ldg(gxp + 2*HID + u2),    gg1 = __ldg(gxp + 2*HID + u2 + 1);
        float go0 = __ldg(gxp + 3*HID + u2),    go1 = __ldg(gxp + 3*HID + u2 + 1);

        float acc[8];
        #pragma unroll
        for (int i = 0; i < 8; i++) acc[i] = 0.0f;

        #pragma unroll
        for (int i = 0; i < 2; i++) {
            size_t go = (size_t)(ar0 + i * 16) * HID + ac0 * 8;
            pa_h[i] = *reinterpret_cast<const uint4*>(wjh + go);
            pa_l[i] = *reinterpret_cast<const uint4*>(wjl + go);
        }
        #pragma unroll
        for (int i = 0; i < 4; i++) {
            size_t go = (size_t)(ar0 + i * 16) * HID + ac0 * 8;
            pb_h[i] = __ldcg(reinterpret_cast<const uint4*>(hbh + go));
            pb_l[i] = __ldcg(reinterpret_cast<const uint4*>(hbl + go));
        }

        for (int kc = 0; kc < 8; kc++) {
            __syncthreads();
            #pragma unroll
            for (int i = 0; i < 2; i++) {
                uint32_t so = swz(ar0 + i * 16, ac0);
                *reinterpret_cast<uint4*>(smem + so) = pa_h[i];
                *reinterpret_cast<uint4*>(smem + OFF_ALO + so) = pa_l[i];
            }
            #pragma unroll
            for (int i = 0; i < 4; i++) {
                uint32_t so = swz(ar0 + i * 16, ac0);
                *reinterpret_cast<uint4*>(smem + OFF_BHI + so) = pb_h[i];
                *reinterpret_cast<uint4*>(smem + OFF_BLO + so) = pb_l[i];
            }
            __syncthreads();

            if (kc < 7) {
                int cb = (kc + 1) * 128 + ac0 * 8;
                #pragma unroll
                for (int i = 0; i < 2; i++) {
                    size_t go = (size_t)(ar0 + i * 16) * HID + cb;
                    pa_h[i] = *reinterpret_cast<const uint4*>(wjh + go);
                    pa_l[i] = *reinterpret_cast<const uint4*>(wjl + go);
                }
                #pragma unroll
                for (int i = 0; i < 4; i++) {
                    size_t go = (size_t)(ar0 + i * 16) * HID + cb;
                    pb_h[i] = __ldcg(reinterpret_cast<const uint4*>(hbh + go));
                    pb_l[i] = __ldcg(reinterpret_cast<const uint4*>(hbl + go));
                }
            }

            const uint32_t sA = sbase;
            const uint32_t sB = sbase + OFF_BHI;
            #pragma unroll
            for (int ks = 0; ks < 8; ks++) {
                int un = ks * 2 + uoff;
                uint32_t aaddr = sA + (uint32_t)(arow * 256 + ((un ^ arsw) << 4));
                uint32_t baddr = sB + (uint32_t)(brow * 256 + ((un ^ brsw) << 4));
                uint32_t ah[4], al[4], bh[4], bl[4];
                ldsm4(ah[0], ah[1], ah[2], ah[3], aaddr);
                ldsm4(al[0], al[1], al[2], al[3], aaddr + OFF_ALO);
                ldsm4(bh[0], bh[1], bh[2], bh[3], baddr);
                ldsm4(bl[0], bl[1], bl[2], bl[3], baddr + (OFF_BLO - OFF_BHI));
                mma16816(acc,     ah, bh[0], bh[2]);
                mma16816(acc,     ah, bl[0], bl[2]);
                mma16816(acc,     al, bh[0], bh[2]);
                mma16816(acc + 4, ah, bh[1], bh[3]);
                mma16816(acc + 4, ah, bl[1], bl[3]);
                mma16816(acc + 4, al, bh[1], bh[3]);
            }
        }
        __syncthreads();

        float* D = reinterpret_cast<float*>(smem);
        {
            int col = nt * 16 + (lane & 3) * 2;
            int row0 = mh * 16 + (lane >> 2);
            *reinterpret_cast<float2*>(&D[row0 * DPITCH + col]) =
                make_float2(acc[0], acc[1]);
            *reinterpret_cast<float2*>(&D[(row0 + 8) * DPITCH + col]) =
                make_float2(acc[2], acc[3]);
            *reinterpret_cast<float2*>(&D[row0 * DPITCH + col + 8]) =
                make_float2(acc[4], acc[5]);
            *reinterpret_cast<float2*>(&D[(row0 + 8) * DPITCH + col + 8]) =
                make_float2(acc[6], acc[7]);
        }
        __syncthreads();

        float pi0 = D[(0*8 + u2) * DPITCH + b] + gx0;
        float pf0 = D[(1*8 + u2) * DPITCH + b] + gf0;
        float pg0 = D[(2*8 + u2) * DPITCH + b] + gg0;
        float po0 = D[(3*8 + u2) * DPITCH + b] + go0;
        float pi1 = D[(0*8 + u2 + 1) * DPITCH + b] + gx1;
        float pf1 = D[(1*8 + u2 + 1) * DPITCH + b] + gf1;
        float pg1 = D[(2*8 + u2 + 1) * DPITCH + b] + gg1;
        float po1 = D[(3*8 + u2 + 1) * DPITCH + b] + go1;

        cs0 = sigf(pf0) * cs0 + sigf(pi0) * tanhf(pg0);
        cs1 = sigf(pf1) * cs1 + sigf(pi1) * tanhf(pg1);
        float h0 = sigf(po0) * tanhf(cs0);
        float h1 = sigf(po1) * tanhf(cs1);

        {
            __nv_bfloat16 h0h = __float2bfloat16(h0);
            __nv_bfloat16 h1h = __float2bfloat16(h1);
            float h0hf = __bfloat162float(h0h);
            float h1hf = __bfloat162float(h1h);
            int wbuf = (t + 1) & 1;
            int idx2 = (b * HID + j * 8 + u2) >> 1;
            __stcg(reinterpret_cast<uint32_t*>(g_hbf_hi[wbuf]) + idx2,
                   pack_bf2(h0hf, h1hf));
            __stcg(reinterpret_cast<uint32_t*>(g_hbf_lo[wbuf]) + idx2,
                   pack_bf2(h0 - h0hf, h1 - h1hf));
        }

        if (layer == 0) {
            *reinterpret_cast<float2*>(
                g_h1 + ((size_t)b * SEQ + t) * HID + j * 8 + u2) =
                make_float2(h0, h1);
        } else {
            float r0 = h0 > 0.0f ? h0 : 0.0f;
            float r1 = h1 > 0.0f ? h1 : 0.0f;
            *reinterpret_cast<float2*>(
                out + ((size_t)b * SEQ + t) * HID + j * 8 + u2) =
                make_float2(sigf(r0), sigf(r1));
        }

        grid_barrier(RCTA);
    }
}

// ---------------------------------------------------------------------------
extern "C" void kernel_launch(void* const* d_in, const int* in_sizes, int n_in,
                              void* d_out, int out_size)
{
    const float* x    = (const float*)d_in[0];
    const float* Wih0 = (const float*)d_in[1];
    const float* Whh0 = (const float*)d_in[2];
    const float* bih0 = (const float*)d_in[3];
    const float* bhh0 = (const float*)d_in[4];
    const float* Wih1 = (const float*)d_in[5];
    const float* Whh1 = (const float*)d_in[6];
    const float* bih1 = (const float*)d_in[7];
    const float* bhh1 = (const float*)d_in[8];
    float* out = (float*)d_out;

    dim3 gg(G4 / 64, MTOT / 128);   // 64 x 128

    // Layer 0
    convert_x<<<2048, 256>>>(x, MTOT * DIN);
    convert_wih<<<2048, 256>>>(Wih0, G4 * DIN);
    convert_w<<<G4, 256>>>(Whh0);
    gemm_hmma<<<gg, 256>>>(bih0, bhh0, DIN);
    lstm_mma<<<RCTA, 256>>>(0, out);

    // Layer 1
    convert_h1<<<2048, 256>>>();
    convert_wih<<<2048, 256>>>(Wih1, G4 * HID);
    convert_w<<<G4, 256>>>(Whh1);
    gemm_hmma<<<gg, 256>>>(bih1, bhh1, HID);
    lstm_mma<<<RCTA, 256>>>(1, out);
}